// round 1
// baseline (speedup 1.0000x reference)
#include <cuda_runtime.h>
#include <math.h>
#include <stdint.h>

// Problem constants (fixed by the dataset)
#define NB 4
#define NV 4000
#define NF 6000
#define IMH 64
#define IMW 64
#define NPIX (NB * IMH * IMW)          // 16384
#define NCHUNK 16
#define FCHUNK ((NF + NCHUNK - 1) / NCHUNK)  // 375
#define RTHREADS 128
#define PPT 4
#define CTA_PIX (RTHREADS * PPT)       // 512
#define NBLKX (NPIX / CTA_PIX)         // 32

#define STEPF (2.0f / 63.0f)

// -------- device scratch (no allocations allowed) --------
__device__ float  g_vscam[NB * NV * 3];
__device__ float  g_vsimg[NB * NV * 2];
__device__ float  g_vnorm[NB * NV * 3];
__device__ float4 g_rec[NB * NF * 3];      // packed raster records
__device__ float  g_fattr[NB * NF * 18];   // per-face per-vertex [normal(3) | attrib(3)]
__device__ float  g_pz[NCHUNK * NPIX];
__device__ int    g_pi[NCHUNK * NPIX];
__device__ float  g_ps[NCHUNK * NPIX];

// -------- kernels --------
__global__ void k_zero_vnorm() {
    int i = blockIdx.x * blockDim.x + threadIdx.x;
    if (i < NB * NV * 3) g_vnorm[i] = 0.0f;
}

__global__ void k_vertices(const float* __restrict__ verts,
                           const float* __restrict__ rot,
                           const float* __restrict__ trans) {
    int i = blockIdx.x * blockDim.x + threadIdx.x;
    if (i >= NB * NV) return;
    int b = i / NV;
    const float* v = verts + (size_t)i * 3;
    const float* R = rot + b * 9;
    const float* t = trans + b * 3;
    float x = v[0], y = v[1], z = v[2];
    // vs_cam[b,v,i] = sum_j vertices[b,v,j] * rot[b,i,j] + trans[b,i]
    float cx = x * R[0] + y * R[1] + z * R[2] + t[0];
    float cy = x * R[3] + y * R[4] + z * R[5] + t[1];
    float cz = x * R[6] + y * R[7] + z * R[8] + t[2];
    g_vscam[i * 3 + 0] = cx;
    g_vscam[i * 3 + 1] = cy;
    g_vscam[i * 3 + 2] = cz;
    g_vsimg[i * 2 + 0] = cx / cz;   // reference: vs_img = xy / z  (per vertex)
    g_vsimg[i * 2 + 1] = cy / cz;
}

__global__ void k_face_prep(const int* __restrict__ faces) {
    int i = blockIdx.x * blockDim.x + threadIdx.x;
    if (i >= NB * NF) return;
    int b = i / NF, f = i % NF;
    int i0 = faces[f * 3 + 0], i1 = faces[f * 3 + 1], i2 = faces[f * 3 + 2];

    const float* c0 = g_vscam + ((size_t)b * NV + i0) * 3;
    const float* c1 = g_vscam + ((size_t)b * NV + i1) * 3;
    const float* c2 = g_vscam + ((size_t)b * NV + i2) * 3;
    float e1x = c1[0] - c0[0], e1y = c1[1] - c0[1], e1z = c1[2] - c0[2];
    float e2x = c2[0] - c0[0], e2y = c2[1] - c0[1], e2z = c2[2] - c0[2];
    float nx = e1y * e2z - e1z * e2y;
    float ny = e1z * e2x - e1x * e2z;
    float nz = e1x * e2y - e1y * e2x;
    atomicAdd(&g_vnorm[((size_t)b * NV + i0) * 3 + 0], nx);
    atomicAdd(&g_vnorm[((size_t)b * NV + i0) * 3 + 1], ny);
    atomicAdd(&g_vnorm[((size_t)b * NV + i0) * 3 + 2], nz);
    atomicAdd(&g_vnorm[((size_t)b * NV + i1) * 3 + 0], nx);
    atomicAdd(&g_vnorm[((size_t)b * NV + i1) * 3 + 1], ny);
    atomicAdd(&g_vnorm[((size_t)b * NV + i1) * 3 + 2], nz);
    atomicAdd(&g_vnorm[((size_t)b * NV + i2) * 3 + 0], nx);
    atomicAdd(&g_vnorm[((size_t)b * NV + i2) * 3 + 1], ny);
    atomicAdd(&g_vnorm[((size_t)b * NV + i2) * 3 + 2], nz);

    const float* p0 = g_vsimg + ((size_t)b * NV + i0) * 2;
    const float* p1 = g_vsimg + ((size_t)b * NV + i1) * 2;
    const float* p2 = g_vsimg + ((size_t)b * NV + i2) * 2;
    float v0x = p0[0], v0y = p0[1];
    float v1x = p1[0], v1y = p1[1];
    float v2x = p2[0], v2y = p2[1];
    // reference: A = (v1x-v0x)(v2y-v0y) - (v1y-v0y)(v2x-v0x); clamp |A|<1e-8 -> +1e-8
    float A = (v1x - v0x) * (v2y - v0y) - (v1y - v0y) * (v2x - v0x);
    if (fabsf(A) < 1e-8f) A = 1e-8f;
    float negT = -0.3f * fabsf(A);              // band threshold: dmin > -0.3
    float sgn  = (A > 0.0f) ? 1.0f : -1.0f;     // exact sign-of-w helper

    float4* r = g_rec + (size_t)i * 3;
    r[0] = make_float4(v0x, v0y, v1x, v1y);
    r[1] = make_float4(v2x, v2y, c0[2], c1[2]);
    r[2] = make_float4(c2[2], A, negT, sgn);
}

__global__ void k_vnorm_normalize() {
    int i = blockIdx.x * blockDim.x + threadIdx.x;
    if (i >= NB * NV) return;
    float x = g_vnorm[i * 3 + 0];
    float y = g_vnorm[i * 3 + 1];
    float z = g_vnorm[i * 3 + 2];
    float d = sqrtf(x * x + y * y + z * z) + 1e-10f;
    g_vnorm[i * 3 + 0] = x / d;
    g_vnorm[i * 3 + 1] = y / d;
    g_vnorm[i * 3 + 2] = z / d;
}

__global__ void k_face_attr(const int* __restrict__ faces,
                            const float* __restrict__ attribs) {
    int i = blockIdx.x * blockDim.x + threadIdx.x;
    if (i >= NB * NF) return;
    int b = i / NF, f = i % NF;
    float* dst = g_fattr + (size_t)i * 18;
    #pragma unroll
    for (int k = 0; k < 3; k++) {
        int vid = faces[f * 3 + k];
        const float* vn = g_vnorm + ((size_t)b * NV + vid) * 3;
        dst[k * 6 + 0] = vn[0];
        dst[k * 6 + 1] = vn[1];
        dst[k * 6 + 2] = vn[2];
        const float* at = attribs + ((size_t)i * 3 + k) * 3;
        dst[k * 6 + 3] = at[0];
        dst[k * 6 + 4] = at[1];
        dst[k * 6 + 5] = at[2];
    }
}

__global__ __launch_bounds__(RTHREADS) void k_raster() {
    const int chunk = blockIdx.y;
    const int pixbase = blockIdx.x * CTA_PIX + threadIdx.x * PPT;
    const int b  = pixbase >> 12;          // / 4096
    const int pp = pixbase & 4095;
    const int iy = pp >> 6, ix = pp & 63;  // 4 consecutive pixels share a row
    const float py = -1.0f + iy * STEPF;
    float px[PPT];
    #pragma unroll
    for (int j = 0; j < PPT; j++) px[j] = -1.0f + (ix + j) * STEPF;

    const float K1  = 1.0f - 1e-7f;
    const float CIN = log1pf(-K1);         // inside-face contribution (constant)

    float S[PPT];
    float zb[PPT];
    int   ib[PPT];
    #pragma unroll
    for (int j = 0; j < PPT; j++) { S[j] = 0.0f; zb[j] = INFINITY; ib[j] = 0x7fffffff; }

    const int f0 = chunk * FCHUNK;
    const int f1 = (f0 + FCHUNK < NF) ? (f0 + FCHUNK) : NF;
    const float4* recb = g_rec + (size_t)b * NF * 3;

    for (int f = f0; f < f1; f++) {
        float4 r0 = recb[f * 3 + 0];
        float4 r1 = recb[f * 3 + 1];
        float4 r2 = recb[f * 3 + 2];
        float v0x = r0.x, v0y = r0.y, v1x = r0.z, v1y = r0.w;
        float v2x = r1.x, v2y = r1.y, z0 = r1.z, z1 = r1.w;
        float z2 = r2.x, A = r2.y, negT = r2.z, sgn = r2.w;

        float dx0 = v2x - v1x, dy0 = v2y - v1y;
        float dx1 = v0x - v2x, dy1 = v0y - v2y;
        float dx2 = v1x - v0x, dy2 = v1y - v0y;
        float q0 = py - v1y, q1 = py - v2y, q2 = py - v0y;   // row-uniform

        #pragma unroll
        for (int j = 0; j < PPT; j++) {
            float a0 = dx0 * q0 - dy0 * (px[j] - v1x);
            float a1 = dx1 * q1 - dy1 * (px[j] - v2x);
            float a2 = dx2 * q2 - dy2 * (px[j] - v0x);
            float b0 = a0 * sgn, b1 = a1 * sgn, b2 = a2 * sgn;
            // cheap band test: all w_i > -0.3  <=>  all b_i > -0.3|A|
            if (fminf(b0, fminf(b1, b2)) > negT) {
                float w0 = a0 / A, w1 = a1 / A, w2 = a2 / A;   // mimic reference division
                bool inside = (b0 >= 0.0f) & (b1 >= 0.0f) & (b2 >= 0.0f); // exact
                if (inside) {
                    S[j] += CIN;
                    float z = w0 * z0 + w1 * z1 + w2 * z2;
                    if (z > 0.0f && z < zb[j]) { zb[j] = z; ib[j] = f; }
                } else {
                    float dmin = fminf(fminf(w0, w1), w2);     // < 0 here
                    float t = fmaxf(dmin / 0.01f, -30.0f);
                    S[j] += log1pf(-(expf(t) * K1));
                }
            }
        }
    }

    #pragma unroll
    for (int j = 0; j < PPT; j++) {
        int p = pixbase + j;
        g_ps[chunk * NPIX + p] = S[j];
        g_pz[chunk * NPIX + p] = zb[j];
        g_pi[chunk * NPIX + p] = ib[j];
    }
}

__global__ void k_combine(float* __restrict__ out) {
    int p = blockIdx.x * blockDim.x + threadIdx.x;
    if (p >= NPIX) return;

    float S = 0.0f;
    float zb = INFINITY;
    int ib = 0x7fffffff;
    #pragma unroll
    for (int c = 0; c < NCHUNK; c++) {
        S += g_ps[c * NPIX + p];
        float z = g_pz[c * NPIX + p];
        int   i = g_pi[c * NPIX + p];
        if (z < zb || (z == zb && i < ib)) { zb = z; ib = i; }  // argmin first-occurrence
    }
    bool covered = (zb < INFINITY);

    int b = p >> 12, pp = p & 4095, iy = pp >> 6, ix = pp & 63;
    float px = -1.0f + ix * STEPF;
    float py = -1.0f + iy * STEPF;

    float on0 = 0.f, on1 = 0.f, on2 = 0.f;
    float oa0 = 0.f, oa1 = 0.f, oa2 = 0.f;
    float fidx = -1.0f;

    if (covered) {
        const float4* r = g_rec + ((size_t)b * NF + ib) * 3;
        float4 r0 = r[0], r1 = r[1], r2 = r[2];
        float v0x = r0.x, v0y = r0.y, v1x = r0.z, v1y = r0.w;
        float v2x = r1.x, v2y = r1.y;
        float A = r2.y;
        float a0 = (v2x - v1x) * (py - v1y) - (v2y - v1y) * (px - v1x);
        float a1 = (v0x - v2x) * (py - v2y) - (v0y - v2y) * (px - v2x);
        float a2 = (v1x - v0x) * (py - v0y) - (v1y - v0y) * (px - v0x);
        float w0 = a0 / A, w1 = a1 / A, w2 = a2 / A;
        const float* at = g_fattr + ((size_t)b * NF + ib) * 18;
        float att[6];
        #pragma unroll
        for (int c = 0; c < 6; c++)
            att[c] = w0 * at[c] + w1 * at[6 + c] + w2 * at[12 + c];
        float nrm = sqrtf(att[0] * att[0] + att[1] * att[1] + att[2] * att[2]) + 1e-10f;
        on0 = att[0] / nrm; on1 = att[1] / nrm; on2 = att[2] / nrm;
        oa0 = att[3]; oa1 = att[4]; oa2 = att[5];
        fidx = (float)ib;
    }
    float improb = 1.0f - expf(S);

    // output layout: imnormal (NPIX*3) | im_attr (NPIX*3) | improb (NPIX) | imdx (NPIX)
    out[p * 3 + 0] = on0;
    out[p * 3 + 1] = on1;
    out[p * 3 + 2] = on2;
    out[NPIX * 3 + p * 3 + 0] = oa0;
    out[NPIX * 3 + p * 3 + 1] = oa1;
    out[NPIX * 3 + p * 3 + 2] = oa2;
    out[NPIX * 6 + p] = improb;
    out[NPIX * 7 + p] = fidx;
}

// -------- launch --------
extern "C" void kernel_launch(void* const* d_in, const int* in_sizes, int n_in,
                              void* d_out, int out_size) {
    const float* vertices = (const float*)d_in[0];
    const int*   faces    = (const int*)d_in[1];
    const float* attribs  = (const float*)d_in[2];
    const float* cam_rot  = (const float*)d_in[3];
    const float* cam_tr   = (const float*)d_in[4];
    (void)in_sizes; (void)n_in; (void)out_size;

    k_zero_vnorm<<<(NB * NV * 3 + 255) / 256, 256>>>();
    k_vertices<<<(NB * NV + 255) / 256, 256>>>(vertices, cam_rot, cam_tr);
    k_face_prep<<<(NB * NF + 255) / 256, 256>>>(faces);
    k_vnorm_normalize<<<(NB * NV + 255) / 256, 256>>>();
    k_face_attr<<<(NB * NF + 255) / 256, 256>>>(faces, attribs);
    k_raster<<<dim3(NBLKX, NCHUNK), RTHREADS>>>();
    k_combine<<<(NPIX + 255) / 256, 256>>>((float*)d_out);
}

// round 2
// speedup vs baseline: 2.7942x; 2.7942x over previous
#include <cuda_runtime.h>
#include <math.h>
#include <stdint.h>

// Problem constants (fixed by the dataset)
#define NB 4
#define NV 4000
#define NF 6000
#define IMH 64
#define IMW 64
#define NPIX (NB * IMH * IMW)          // 16384
#define NCHUNK 24
#define FCHUNK ((NF + NCHUNK - 1) / NCHUNK)  // 250
#define NTILES (NB * 16)               // 4x4 tiles of 16x16 px per image -> 64

#define STEPF (2.0f / 63.0f)

// -------- device scratch (no allocations allowed) --------
__device__ float  g_vscam[NB * NV * 3];
__device__ float  g_vsimg[NB * NV * 2];
__device__ float  g_vnorm[NB * NV * 3];
__device__ float4 g_rec[NB * NF * 3];      // packed raster records
__device__ float4 g_bbox[NB * NF];         // dilated bbox (xmin,xmax,ymin,ymax)
__device__ float  g_fattr[NB * NF * 18];   // per-face per-vertex [normal(3) | attrib(3)]
__device__ float  g_pz[NCHUNK * NPIX];
__device__ int    g_pi[NCHUNK * NPIX];
__device__ float  g_ps[NCHUNK * NPIX];

// -------- kernels --------
__global__ void k_vertices(const float* __restrict__ verts,
                           const float* __restrict__ rot,
                           const float* __restrict__ trans) {
    int i = blockIdx.x * blockDim.x + threadIdx.x;
    if (i >= NB * NV) return;
    int b = i / NV;
    const float* v = verts + (size_t)i * 3;
    const float* R = rot + b * 9;
    const float* t = trans + b * 3;
    float x = v[0], y = v[1], z = v[2];
    float cx = x * R[0] + y * R[1] + z * R[2] + t[0];
    float cy = x * R[3] + y * R[4] + z * R[5] + t[1];
    float cz = x * R[6] + y * R[7] + z * R[8] + t[2];
    g_vscam[i * 3 + 0] = cx;
    g_vscam[i * 3 + 1] = cy;
    g_vscam[i * 3 + 2] = cz;
    g_vsimg[i * 2 + 0] = cx / cz;
    g_vsimg[i * 2 + 1] = cy / cz;
    // zero vnorm accumulators (fused; completes before next launch)
    g_vnorm[i * 3 + 0] = 0.0f;
    g_vnorm[i * 3 + 1] = 0.0f;
    g_vnorm[i * 3 + 2] = 0.0f;
}

__global__ void k_face_prep(const int* __restrict__ faces) {
    int i = blockIdx.x * blockDim.x + threadIdx.x;
    if (i >= NB * NF) return;
    int b = i / NF, f = i % NF;
    int i0 = faces[f * 3 + 0], i1 = faces[f * 3 + 1], i2 = faces[f * 3 + 2];

    const float* c0 = g_vscam + ((size_t)b * NV + i0) * 3;
    const float* c1 = g_vscam + ((size_t)b * NV + i1) * 3;
    const float* c2 = g_vscam + ((size_t)b * NV + i2) * 3;
    float e1x = c1[0] - c0[0], e1y = c1[1] - c0[1], e1z = c1[2] - c0[2];
    float e2x = c2[0] - c0[0], e2y = c2[1] - c0[1], e2z = c2[2] - c0[2];
    float nx = e1y * e2z - e1z * e2y;
    float ny = e1z * e2x - e1x * e2z;
    float nz = e1x * e2y - e1y * e2x;
    atomicAdd(&g_vnorm[((size_t)b * NV + i0) * 3 + 0], nx);
    atomicAdd(&g_vnorm[((size_t)b * NV + i0) * 3 + 1], ny);
    atomicAdd(&g_vnorm[((size_t)b * NV + i0) * 3 + 2], nz);
    atomicAdd(&g_vnorm[((size_t)b * NV + i1) * 3 + 0], nx);
    atomicAdd(&g_vnorm[((size_t)b * NV + i1) * 3 + 1], ny);
    atomicAdd(&g_vnorm[((size_t)b * NV + i1) * 3 + 2], nz);
    atomicAdd(&g_vnorm[((size_t)b * NV + i2) * 3 + 0], nx);
    atomicAdd(&g_vnorm[((size_t)b * NV + i2) * 3 + 1], ny);
    atomicAdd(&g_vnorm[((size_t)b * NV + i2) * 3 + 2], nz);

    const float* p0 = g_vsimg + ((size_t)b * NV + i0) * 2;
    const float* p1 = g_vsimg + ((size_t)b * NV + i1) * 2;
    const float* p2 = g_vsimg + ((size_t)b * NV + i2) * 2;
    float v0x = p0[0], v0y = p0[1];
    float v1x = p1[0], v1y = p1[1];
    float v2x = p2[0], v2y = p2[1];
    float A = (v1x - v0x) * (v2y - v0y) - (v1y - v0y) * (v2x - v0x);
    if (fabsf(A) < 1e-8f) A = 1e-8f;
    float invA = 1.0f / A;                     // IEEE div (exact, once per face)
    float sgn  = (A > 0.0f) ? 1.0f : -1.0f;

    float4* r = g_rec + (size_t)i * 3;
    r[0] = make_float4(v0x, v0y, v1x, v1y);
    r[1] = make_float4(v2x, v2y, c0[2], c1[2]);
    r[2] = make_float4(c2[2], A, invA, sgn);

    // dilated bbox: {min_i w_i >= -0.3} == triangle scaled x1.9 about centroid
    float cx = (v0x + v1x + v2x) * 0.33333334f;
    float cy = (v0y + v1y + v2y) * 0.33333334f;
    float xmn = fminf(v0x, fminf(v1x, v2x)), xmx = fmaxf(v0x, fmaxf(v1x, v2x));
    float ymn = fminf(v0y, fminf(v1y, v2y)), ymx = fmaxf(v0y, fmaxf(v1y, v2y));
    const float SC = 1.91f, EPS = 1e-3f;
    g_bbox[i] = make_float4(cx + SC * (xmn - cx) - EPS,
                            cx + SC * (xmx - cx) + EPS,
                            cy + SC * (ymn - cy) - EPS,
                            cy + SC * (ymx - cy) + EPS);
}

__global__ void k_face_attr(const int* __restrict__ faces,
                            const float* __restrict__ attribs) {
    int i = blockIdx.x * blockDim.x + threadIdx.x;
    if (i >= NB * NF) return;
    int b = i / NF, f = i % NF;
    float* dst = g_fattr + (size_t)i * 18;
    #pragma unroll
    for (int k = 0; k < 3; k++) {
        int vid = faces[f * 3 + k];
        const float* vn = g_vnorm + ((size_t)b * NV + vid) * 3;
        // normalize inline (same expression per vertex -> bitwise identical)
        float x = vn[0], y = vn[1], z = vn[2];
        float d = sqrtf(x * x + y * y + z * z) + 1e-10f;
        dst[k * 6 + 0] = x / d;
        dst[k * 6 + 1] = y / d;
        dst[k * 6 + 2] = z / d;
        const float* at = attribs + ((size_t)i * 3 + k) * 3;
        dst[k * 6 + 3] = at[0];
        dst[k * 6 + 4] = at[1];
        dst[k * 6 + 5] = at[2];
    }
}

__global__ __launch_bounds__(256) void k_raster() {
    const int tile  = blockIdx.x;              // 0..NTILES-1
    const int chunk = blockIdx.y;              // 0..NCHUNK-1
    const int b  = tile >> 4;
    const int t  = tile & 15;
    const int tx = (t & 3) << 4, ty = (t >> 2) << 4;
    const int lx = threadIdx.x & 15, ly = threadIdx.x >> 4;
    const int ix = tx + lx, iy = ty + ly;
    const float px = -1.0f + ix * STEPF;
    const float py = -1.0f + iy * STEPF;
    const float tminx = -1.0f + tx * STEPF, tmaxx = tminx + 15.0f * STEPF;
    const float tminy = -1.0f + ty * STEPF, tmaxy = tminy + 15.0f * STEPF;

    __shared__ int   s_cnt;
    __shared__ short s_list[FCHUNK];
    if (threadIdx.x == 0) s_cnt = 0;
    __syncthreads();

    const int f0 = chunk * FCHUNK;
    const int f1 = (f0 + FCHUNK < NF) ? (f0 + FCHUNK) : NF;
    const float4* bb = g_bbox + (size_t)b * NF;
    for (int f = f0 + threadIdx.x; f < f1; f += 256) {
        float4 box = bb[f];   // (xmin,xmax,ymin,ymax)
        if (box.x <= tmaxx && box.y >= tminx && box.z <= tmaxy && box.w >= tminy) {
            int k = atomicAdd(&s_cnt, 1);
            s_list[k] = (short)f;
        }
    }
    __syncthreads();
    const int cnt = s_cnt;

    const float K1  = 1.0f - 1e-7f;
    const float CIN = log1pf(-K1);           // inside-face contribution

    float S = 0.0f;
    float zb = INFINITY;
    int   ib = 0x7fffffff;

    const float4* recb = g_rec + (size_t)b * NF * 3;
    for (int i = 0; i < cnt; i++) {
        int f = s_list[i];
        float4 r0 = recb[f * 3 + 0];
        float4 r1 = recb[f * 3 + 1];
        float4 r2 = recb[f * 3 + 2];
        float v0x = r0.x, v0y = r0.y, v1x = r0.z, v1y = r0.w;
        float v2x = r1.x, v2y = r1.y, z0 = r1.z, z1 = r1.w;
        float z2 = r2.x, A = r2.y, invA = r2.z, sgn = r2.w;

        float a0 = (v2x - v1x) * (py - v1y) - (v2y - v1y) * (px - v1x);
        float a1 = (v0x - v2x) * (py - v2y) - (v0y - v2y) * (px - v2x);
        float a2 = (v1x - v0x) * (py - v0y) - (v1y - v0y) * (px - v0x);
        float c0 = a0 * sgn, c1 = a1 * sgn, c2 = a2 * sgn;  // exact sign helpers
        float cmin = fminf(c0, fminf(c1, c2));
        float invAbs = invA * sgn;                           // 1/|A| (exact flip)
        float dmin = cmin * invAbs;                          // = min_i (a_i/A) up to ulps
        if (dmin > -0.3f) {
            if (cmin >= 0.0f) {
                // inside: keep argmin-critical z path with exact IEEE divisions
                S += CIN;
                float w0 = a0 / A, w1 = a1 / A, w2 = a2 / A;
                float z = w0 * z0 + w1 * z1 + w2 * z2;
                if (z > 0.0f && z < zb) { zb = z; ib = f; }
            } else {
                float tt = fmaxf(dmin * 100.0f, -30.0f);
                float p = __expf(tt) * K1;
                if (p < 0.25f) {
                    // ln(1-p) 5-term series, |err| < 4e-5
                    S -= p * (1.0f + p * (0.5f + p * (0.33333334f + p * (0.25f + p * 0.2f))));
                } else {
                    S += log1pf(-p);
                }
            }
        }
    }

    int p = (b << 12) + (iy << 6) + ix;
    g_ps[chunk * NPIX + p] = S;
    g_pz[chunk * NPIX + p] = zb;
    g_pi[chunk * NPIX + p] = ib;
}

__global__ void k_combine(float* __restrict__ out) {
    int p = blockIdx.x * blockDim.x + threadIdx.x;
    if (p >= NPIX) return;

    float S = 0.0f;
    float zb = INFINITY;
    int ib = 0x7fffffff;
    #pragma unroll
    for (int c = 0; c < NCHUNK; c++) {
        S += g_ps[c * NPIX + p];
        float z = g_pz[c * NPIX + p];
        int   i = g_pi[c * NPIX + p];
        if (z < zb || (z == zb && i < ib)) { zb = z; ib = i; }
    }
    bool covered = (zb < INFINITY);

    int b = p >> 12, pp = p & 4095, iy = pp >> 6, ix = pp & 63;
    float px = -1.0f + ix * STEPF;
    float py = -1.0f + iy * STEPF;

    float on0 = 0.f, on1 = 0.f, on2 = 0.f;
    float oa0 = 0.f, oa1 = 0.f, oa2 = 0.f;
    float fidx = -1.0f;

    if (covered) {
        const float4* r = g_rec + ((size_t)b * NF + ib) * 3;
        float4 r0 = r[0], r1 = r[1], r2 = r[2];
        float v0x = r0.x, v0y = r0.y, v1x = r0.z, v1y = r0.w;
        float v2x = r1.x, v2y = r1.y;
        float A = r2.y;
        float a0 = (v2x - v1x) * (py - v1y) - (v2y - v1y) * (px - v1x);
        float a1 = (v0x - v2x) * (py - v2y) - (v0y - v2y) * (px - v2x);
        float a2 = (v1x - v0x) * (py - v0y) - (v1y - v0y) * (px - v0x);
        float w0 = a0 / A, w1 = a1 / A, w2 = a2 / A;
        const float* at = g_fattr + ((size_t)b * NF + ib) * 18;
        float att[6];
        #pragma unroll
        for (int c = 0; c < 6; c++)
            att[c] = w0 * at[c] + w1 * at[6 + c] + w2 * at[12 + c];
        float nrm = sqrtf(att[0] * att[0] + att[1] * att[1] + att[2] * att[2]) + 1e-10f;
        on0 = att[0] / nrm; on1 = att[1] / nrm; on2 = att[2] / nrm;
        oa0 = att[3]; oa1 = att[4]; oa2 = att[5];
        fidx = (float)ib;
    }
    float improb = 1.0f - expf(S);

    out[p * 3 + 0] = on0;
    out[p * 3 + 1] = on1;
    out[p * 3 + 2] = on2;
    out[NPIX * 3 + p * 3 + 0] = oa0;
    out[NPIX * 3 + p * 3 + 1] = oa1;
    out[NPIX * 3 + p * 3 + 2] = oa2;
    out[NPIX * 6 + p] = improb;
    out[NPIX * 7 + p] = fidx;
}

// -------- launch --------
extern "C" void kernel_launch(void* const* d_in, const int* in_sizes, int n_in,
                              void* d_out, int out_size) {
    const float* vertices = (const float*)d_in[0];
    const int*   faces    = (const int*)d_in[1];
    const float* attribs  = (const float*)d_in[2];
    const float* cam_rot  = (const float*)d_in[3];
    const float* cam_tr   = (const float*)d_in[4];
    (void)in_sizes; (void)n_in; (void)out_size;

    k_vertices<<<(NB * NV + 255) / 256, 256>>>(vertices, cam_rot, cam_tr);
    k_face_prep<<<(NB * NF + 255) / 256, 256>>>(faces);
    k_face_attr<<<(NB * NF + 255) / 256, 256>>>(faces, attribs);
    k_raster<<<dim3(NTILES, NCHUNK), 256>>>();
    k_combine<<<(NPIX + 255) / 256, 256>>>((float*)d_out);
}

// round 3
// speedup vs baseline: 3.5469x; 1.2694x over previous
#include <cuda_runtime.h>
#include <math.h>
#include <stdint.h>

// Problem constants (fixed by the dataset)
#define NB 4
#define NV 4000
#define NF 6000
#define IMH 64
#define IMW 64
#define NPIX (NB * IMH * IMW)          // 16384
#define NCHUNK 24
#define FCHUNK ((NF + NCHUNK - 1) / NCHUNK)  // 250
#define NTILES (NB * 16)               // 4x4 tiles of 16x16 px per image -> 64

#define STEPF (2.0f / 63.0f)

// -------- device scratch (no allocations allowed) --------
__device__ float  g_vscam[NB * NV * 3];
__device__ float  g_vsimg[NB * NV * 2];
__device__ float  g_vnorm[NB * NV * 3];
__device__ float4 g_rec[NB * NF * 3];      // packed raster records
__device__ float4 g_bbox[NB * NF];         // dilated bbox (xmin,xmax,ymin,ymax)
__device__ float  g_fattr[NB * NF * 18];   // per-face per-vertex [normal(3) | attrib(3)]
__device__ float  g_pz[NCHUNK * NPIX];
__device__ int    g_pi[NCHUNK * NPIX];
__device__ float  g_ps[NCHUNK * NPIX];

// -------- kernels --------
__global__ void k_vertices(const float* __restrict__ verts,
                           const float* __restrict__ rot,
                           const float* __restrict__ trans) {
    int i = blockIdx.x * blockDim.x + threadIdx.x;
    if (i >= NB * NV) return;
    int b = i / NV;
    const float* v = verts + (size_t)i * 3;
    const float* R = rot + b * 9;
    const float* t = trans + b * 3;
    float x = v[0], y = v[1], z = v[2];
    float cx = x * R[0] + y * R[1] + z * R[2] + t[0];
    float cy = x * R[3] + y * R[4] + z * R[5] + t[1];
    float cz = x * R[6] + y * R[7] + z * R[8] + t[2];
    g_vscam[i * 3 + 0] = cx;
    g_vscam[i * 3 + 1] = cy;
    g_vscam[i * 3 + 2] = cz;
    g_vsimg[i * 2 + 0] = cx / cz;
    g_vsimg[i * 2 + 1] = cy / cz;
    g_vnorm[i * 3 + 0] = 0.0f;
    g_vnorm[i * 3 + 1] = 0.0f;
    g_vnorm[i * 3 + 2] = 0.0f;
}

__global__ void k_face_prep(const int* __restrict__ faces) {
    int i = blockIdx.x * blockDim.x + threadIdx.x;
    if (i >= NB * NF) return;
    int b = i / NF, f = i % NF;
    int i0 = faces[f * 3 + 0], i1 = faces[f * 3 + 1], i2 = faces[f * 3 + 2];

    const float* c0 = g_vscam + ((size_t)b * NV + i0) * 3;
    const float* c1 = g_vscam + ((size_t)b * NV + i1) * 3;
    const float* c2 = g_vscam + ((size_t)b * NV + i2) * 3;
    float e1x = c1[0] - c0[0], e1y = c1[1] - c0[1], e1z = c1[2] - c0[2];
    float e2x = c2[0] - c0[0], e2y = c2[1] - c0[1], e2z = c2[2] - c0[2];
    float nx = e1y * e2z - e1z * e2y;
    float ny = e1z * e2x - e1x * e2z;
    float nz = e1x * e2y - e1y * e2x;
    atomicAdd(&g_vnorm[((size_t)b * NV + i0) * 3 + 0], nx);
    atomicAdd(&g_vnorm[((size_t)b * NV + i0) * 3 + 1], ny);
    atomicAdd(&g_vnorm[((size_t)b * NV + i0) * 3 + 2], nz);
    atomicAdd(&g_vnorm[((size_t)b * NV + i1) * 3 + 0], nx);
    atomicAdd(&g_vnorm[((size_t)b * NV + i1) * 3 + 1], ny);
    atomicAdd(&g_vnorm[((size_t)b * NV + i1) * 3 + 2], nz);
    atomicAdd(&g_vnorm[((size_t)b * NV + i2) * 3 + 0], nx);
    atomicAdd(&g_vnorm[((size_t)b * NV + i2) * 3 + 1], ny);
    atomicAdd(&g_vnorm[((size_t)b * NV + i2) * 3 + 2], nz);

    const float* p0 = g_vsimg + ((size_t)b * NV + i0) * 2;
    const float* p1 = g_vsimg + ((size_t)b * NV + i1) * 2;
    const float* p2 = g_vsimg + ((size_t)b * NV + i2) * 2;
    float v0x = p0[0], v0y = p0[1];
    float v1x = p1[0], v1y = p1[1];
    float v2x = p2[0], v2y = p2[1];
    float A = (v1x - v0x) * (v2y - v0y) - (v1y - v0y) * (v2x - v0x);
    if (fabsf(A) < 1e-8f) A = 1e-8f;
    float invA = 1.0f / A;
    float sgn  = (A > 0.0f) ? 1.0f : -1.0f;

    float4* r = g_rec + (size_t)i * 3;
    r[0] = make_float4(v0x, v0y, v1x, v1y);
    r[1] = make_float4(v2x, v2y, c0[2], c1[2]);
    r[2] = make_float4(c2[2], A, invA, sgn);

    // dilated bbox: {min_i w_i >= -0.3} == triangle scaled x1.9 about centroid
    float cx = (v0x + v1x + v2x) * 0.33333334f;
    float cy = (v0y + v1y + v2y) * 0.33333334f;
    float xmn = fminf(v0x, fminf(v1x, v2x)), xmx = fmaxf(v0x, fmaxf(v1x, v2x));
    float ymn = fminf(v0y, fminf(v1y, v2y)), ymx = fmaxf(v0y, fmaxf(v1y, v2y));
    const float SC = 1.91f, EPS = 1e-3f;
    g_bbox[i] = make_float4(cx + SC * (xmn - cx) - EPS,
                            cx + SC * (xmx - cx) + EPS,
                            cy + SC * (ymn - cy) - EPS,
                            cy + SC * (ymx - cy) + EPS);
}

__global__ void k_face_attr(const int* __restrict__ faces,
                            const float* __restrict__ attribs) {
    int i = blockIdx.x * blockDim.x + threadIdx.x;
    if (i >= NB * NF) return;
    int b = i / NF, f = i % NF;
    float* dst = g_fattr + (size_t)i * 18;
    #pragma unroll
    for (int k = 0; k < 3; k++) {
        int vid = faces[f * 3 + k];
        const float* vn = g_vnorm + ((size_t)b * NV + vid) * 3;
        float x = vn[0], y = vn[1], z = vn[2];
        float d = sqrtf(x * x + y * y + z * z) + 1e-10f;
        dst[k * 6 + 0] = x / d;
        dst[k * 6 + 1] = y / d;
        dst[k * 6 + 2] = z / d;
        const float* at = attribs + ((size_t)i * 3 + k) * 3;
        dst[k * 6 + 3] = at[0];
        dst[k * 6 + 4] = at[1];
        dst[k * 6 + 5] = at[2];
    }
}

__global__ __launch_bounds__(256) void k_raster() {
    const int tile  = blockIdx.x;              // 0..NTILES-1
    const int chunk = blockIdx.y;              // 0..NCHUNK-1
    const int b  = tile >> 4;
    const int t  = tile & 15;
    const int tx = (t & 3) << 4, ty = (t >> 2) << 4;

    // warp-region mapping: warp w -> 8x4 pixel block; lane -> pixel inside it
    const int w    = threadIdx.x >> 5;
    const int lane = threadIdx.x & 31;
    const int wx = (w & 1) << 3;      // 0 or 8
    const int wy = (w >> 1) << 2;     // 0,4,8,12
    const int lx = lane & 7, ly = lane >> 3;
    const int ix = tx + wx + lx, iy = ty + wy + ly;
    const float px = -1.0f + ix * STEPF;
    const float py = -1.0f + iy * STEPF;
    // warp-region bounds (uniform within warp)
    const float wminx = -1.0f + (tx + wx) * STEPF, wmaxx = wminx + 7.0f * STEPF;
    const float wminy = -1.0f + (ty + wy) * STEPF, wmaxy = wminy + 3.0f * STEPF;
    // tile bounds
    const float tminx = -1.0f + tx * STEPF, tmaxx = tminx + 15.0f * STEPF;
    const float tminy = -1.0f + ty * STEPF, tmaxy = tminy + 15.0f * STEPF;

    __shared__ int    s_cnt;
    __shared__ float4 s_r0[FCHUNK];
    __shared__ float4 s_r1[FCHUNK];
    __shared__ float4 s_r2[FCHUNK];
    __shared__ float4 s_box[FCHUNK];
    __shared__ short  s_f[FCHUNK];
    if (threadIdx.x == 0) s_cnt = 0;
    __syncthreads();

    const int f0 = chunk * FCHUNK;
    const int f1 = (f0 + FCHUNK < NF) ? (f0 + FCHUNK) : NF;
    const float4* bb   = g_bbox + (size_t)b * NF;
    const float4* recb = g_rec + (size_t)b * NF * 3;
    for (int f = f0 + threadIdx.x; f < f1; f += 256) {
        float4 box = bb[f];   // (xmin,xmax,ymin,ymax)
        if (box.x <= tmaxx && box.y >= tminx && box.z <= tmaxy && box.w >= tminy) {
            int k = atomicAdd(&s_cnt, 1);
            s_box[k] = box;
            s_f[k] = (short)f;
            s_r0[k] = recb[f * 3 + 0];
            s_r1[k] = recb[f * 3 + 1];
            s_r2[k] = recb[f * 3 + 2];
        }
    }
    __syncthreads();
    const int cnt = s_cnt;

    const float K1  = 1.0f - 1e-7f;
    const float CIN = log1pf(-K1);           // inside-face contribution

    float S = 0.0f;
    float zb = INFINITY;
    int   ib = 0x7fffffff;

    #pragma unroll 2
    for (int i = 0; i < cnt; i++) {
        float4 box = s_box[i];
        // warp-uniform rejection against this warp's 8x4 region
        if (box.x > wmaxx || box.y < wminx || box.z > wmaxy || box.w < wminy) continue;
        // per-pixel bbox rejection
        if (px < box.x || px > box.y || py < box.z || py > box.w) continue;

        float4 r0 = s_r0[i];
        float4 r1 = s_r1[i];
        float4 r2 = s_r2[i];
        float v0x = r0.x, v0y = r0.y, v1x = r0.z, v1y = r0.w;
        float v2x = r1.x, v2y = r1.y, z0 = r1.z, z1 = r1.w;
        float z2 = r2.x, A = r2.y, invA = r2.z, sgn = r2.w;

        float a0 = (v2x - v1x) * (py - v1y) - (v2y - v1y) * (px - v1x);
        float a1 = (v0x - v2x) * (py - v2y) - (v0y - v2y) * (px - v2x);
        float a2 = (v1x - v0x) * (py - v0y) - (v1y - v0y) * (px - v0x);
        float c0 = a0 * sgn, c1 = a1 * sgn, c2 = a2 * sgn;  // exact sign helpers
        float cmin = fminf(c0, fminf(c1, c2));
        float invAbs = invA * sgn;                           // 1/|A| (exact flip)
        float dmin = cmin * invAbs;                          // = min_i (a_i/A) up to ulps
        if (dmin > -0.3f) {
            if (cmin >= 0.0f) {
                // inside: argmin-critical z path with exact IEEE divisions
                S += CIN;
                float w0 = a0 / A, w1 = a1 / A, w2 = a2 / A;
                float z = w0 * z0 + w1 * z1 + w2 * z2;
                int f = s_f[i];
                if (z > 0.0f && (z < zb || (z == zb && f < ib))) { zb = z; ib = f; }
            } else {
                float tt = fmaxf(dmin * 100.0f, -30.0f);
                float p = __expf(tt) * K1;
                if (p < 0.25f) {
                    S -= p * (1.0f + p * (0.5f + p * (0.33333334f + p * (0.25f + p * 0.2f))));
                } else {
                    S += log1pf(-p);
                }
            }
        }
    }

    int p = (b << 12) + (iy << 6) + ix;
    g_ps[chunk * NPIX + p] = S;
    g_pz[chunk * NPIX + p] = zb;
    g_pi[chunk * NPIX + p] = ib;
}

__global__ void k_combine(float* __restrict__ out) {
    int p = blockIdx.x * blockDim.x + threadIdx.x;
    if (p >= NPIX) return;

    float S = 0.0f;
    float zb = INFINITY;
    int ib = 0x7fffffff;
    #pragma unroll
    for (int c = 0; c < NCHUNK; c++) {
        S += g_ps[c * NPIX + p];
        float z = g_pz[c * NPIX + p];
        int   i = g_pi[c * NPIX + p];
        if (z < zb || (z == zb && i < ib)) { zb = z; ib = i; }
    }
    bool covered = (zb < INFINITY);

    int b = p >> 12, pp = p & 4095, iy = pp >> 6, ix = pp & 63;
    float px = -1.0f + ix * STEPF;
    float py = -1.0f + iy * STEPF;

    float on0 = 0.f, on1 = 0.f, on2 = 0.f;
    float oa0 = 0.f, oa1 = 0.f, oa2 = 0.f;
    float fidx = -1.0f;

    if (covered) {
        const float4* r = g_rec + ((size_t)b * NF + ib) * 3;
        float4 r0 = r[0], r1 = r[1], r2 = r[2];
        float v0x = r0.x, v0y = r0.y, v1x = r0.z, v1y = r0.w;
        float v2x = r1.x, v2y = r1.y;
        float A = r2.y;
        float a0 = (v2x - v1x) * (py - v1y) - (v2y - v1y) * (px - v1x);
        float a1 = (v0x - v2x) * (py - v2y) - (v0y - v2y) * (px - v2x);
        float a2 = (v1x - v0x) * (py - v0y) - (v1y - v0y) * (px - v0x);
        float w0 = a0 / A, w1 = a1 / A, w2 = a2 / A;
        const float* at = g_fattr + ((size_t)b * NF + ib) * 18;
        float att[6];
        #pragma unroll
        for (int c = 0; c < 6; c++)
            att[c] = w0 * at[c] + w1 * at[6 + c] + w2 * at[12 + c];
        float nrm = sqrtf(att[0] * att[0] + att[1] * att[1] + att[2] * att[2]) + 1e-10f;
        on0 = att[0] / nrm; on1 = att[1] / nrm; on2 = att[2] / nrm;
        oa0 = att[3]; oa1 = att[4]; oa2 = att[5];
        fidx = (float)ib;
    }
    float improb = 1.0f - expf(S);

    out[p * 3 + 0] = on0;
    out[p * 3 + 1] = on1;
    out[p * 3 + 2] = on2;
    out[NPIX * 3 + p * 3 + 0] = oa0;
    out[NPIX * 3 + p * 3 + 1] = oa1;
    out[NPIX * 3 + p * 3 + 2] = oa2;
    out[NPIX * 6 + p] = improb;
    out[NPIX * 7 + p] = fidx;
}

// -------- launch --------
extern "C" void kernel_launch(void* const* d_in, const int* in_sizes, int n_in,
                              void* d_out, int out_size) {
    const float* vertices = (const float*)d_in[0];
    const int*   faces    = (const int*)d_in[1];
    const float* attribs  = (const float*)d_in[2];
    const float* cam_rot  = (const float*)d_in[3];
    const float* cam_tr   = (const float*)d_in[4];
    (void)in_sizes; (void)n_in; (void)out_size;

    k_vertices<<<(NB * NV + 255) / 256, 256>>>(vertices, cam_rot, cam_tr);
    k_face_prep<<<(NB * NF + 255) / 256, 256>>>(faces);
    k_face_attr<<<(NB * NF + 255) / 256, 256>>>(faces, attribs);
    k_raster<<<dim3(NTILES, NCHUNK), 256>>>();
    k_combine<<<(NPIX + 255) / 256, 256>>>((float*)d_out);
}

// round 4
// speedup vs baseline: 6.4231x; 1.8109x over previous
#include <cuda_runtime.h>
#include <math.h>
#include <stdint.h>

// Problem constants (fixed by the dataset)
#define NB 4
#define NV 4000
#define NF 6000
#define IMH 64
#define IMW 64
#define NPIX (NB * IMH * IMW)          // 16384
#define NCHUNK 24
#define FCHUNK ((NF + NCHUNK - 1) / NCHUNK)  // 250
#define TILES_PER_IMG 64               // 8x8 grid of 8x8-pixel tiles
#define NTILES (NB * TILES_PER_IMG)    // 256

#define STEPF (2.0f / 63.0f)

// -------- device scratch (no allocations allowed) --------
__device__ float  g_vscam[NB * NV * 3];
__device__ float  g_vsimg[NB * NV * 2];
__device__ float  g_vnorm[NB * NV * 3];
__device__ float4 g_rec[NB * NF * 3];      // packed raster records
__device__ float4 g_bbox[NB * NF];         // dilated bbox (xmin,xmax,ymin,ymax)
__device__ float  g_fattr[NB * NF * 18];   // per-face per-vertex [normal(3) | attrib(3)]
__device__ float  g_pz[NCHUNK * NPIX];
__device__ int    g_pi[NCHUNK * NPIX];
__device__ float  g_ps[NCHUNK * NPIX];

// -------- kernels --------
__global__ void k_vertices(const float* __restrict__ verts,
                           const float* __restrict__ rot,
                           const float* __restrict__ trans) {
    int i = blockIdx.x * blockDim.x + threadIdx.x;
    if (i >= NB * NV) return;
    int b = i / NV;
    const float* v = verts + (size_t)i * 3;
    const float* R = rot + b * 9;
    const float* t = trans + b * 3;
    float x = v[0], y = v[1], z = v[2];
    float cx = x * R[0] + y * R[1] + z * R[2] + t[0];
    float cy = x * R[3] + y * R[4] + z * R[5] + t[1];
    float cz = x * R[6] + y * R[7] + z * R[8] + t[2];
    g_vscam[i * 3 + 0] = cx;
    g_vscam[i * 3 + 1] = cy;
    g_vscam[i * 3 + 2] = cz;
    g_vsimg[i * 2 + 0] = cx / cz;
    g_vsimg[i * 2 + 1] = cy / cz;
    g_vnorm[i * 3 + 0] = 0.0f;
    g_vnorm[i * 3 + 1] = 0.0f;
    g_vnorm[i * 3 + 2] = 0.0f;
}

__global__ void k_face_prep(const int* __restrict__ faces) {
    int i = blockIdx.x * blockDim.x + threadIdx.x;
    if (i >= NB * NF) return;
    int b = i / NF, f = i % NF;
    int i0 = faces[f * 3 + 0], i1 = faces[f * 3 + 1], i2 = faces[f * 3 + 2];

    const float* c0 = g_vscam + ((size_t)b * NV + i0) * 3;
    const float* c1 = g_vscam + ((size_t)b * NV + i1) * 3;
    const float* c2 = g_vscam + ((size_t)b * NV + i2) * 3;
    float e1x = c1[0] - c0[0], e1y = c1[1] - c0[1], e1z = c1[2] - c0[2];
    float e2x = c2[0] - c0[0], e2y = c2[1] - c0[1], e2z = c2[2] - c0[2];
    float nx = e1y * e2z - e1z * e2y;
    float ny = e1z * e2x - e1x * e2z;
    float nz = e1x * e2y - e1y * e2x;
    atomicAdd(&g_vnorm[((size_t)b * NV + i0) * 3 + 0], nx);
    atomicAdd(&g_vnorm[((size_t)b * NV + i0) * 3 + 1], ny);
    atomicAdd(&g_vnorm[((size_t)b * NV + i0) * 3 + 2], nz);
    atomicAdd(&g_vnorm[((size_t)b * NV + i1) * 3 + 0], nx);
    atomicAdd(&g_vnorm[((size_t)b * NV + i1) * 3 + 1], ny);
    atomicAdd(&g_vnorm[((size_t)b * NV + i1) * 3 + 2], nz);
    atomicAdd(&g_vnorm[((size_t)b * NV + i2) * 3 + 0], nx);
    atomicAdd(&g_vnorm[((size_t)b * NV + i2) * 3 + 1], ny);
    atomicAdd(&g_vnorm[((size_t)b * NV + i2) * 3 + 2], nz);

    const float* p0 = g_vsimg + ((size_t)b * NV + i0) * 2;
    const float* p1 = g_vsimg + ((size_t)b * NV + i1) * 2;
    const float* p2 = g_vsimg + ((size_t)b * NV + i2) * 2;
    float v0x = p0[0], v0y = p0[1];
    float v1x = p1[0], v1y = p1[1];
    float v2x = p2[0], v2y = p2[1];
    float A = (v1x - v0x) * (v2y - v0y) - (v1y - v0y) * (v2x - v0x);
    if (fabsf(A) < 1e-8f) A = 1e-8f;
    float invA = 1.0f / A;
    float sgn  = (A > 0.0f) ? 1.0f : -1.0f;

    float4* r = g_rec + (size_t)i * 3;
    r[0] = make_float4(v0x, v0y, v1x, v1y);
    r[1] = make_float4(v2x, v2y, c0[2], c1[2]);
    r[2] = make_float4(c2[2], A, invA, sgn);

    // dilated bbox: {min_i w_i >= -0.3} == triangle scaled x1.9 about centroid
    float cx = (v0x + v1x + v2x) * 0.33333334f;
    float cy = (v0y + v1y + v2y) * 0.33333334f;
    float xmn = fminf(v0x, fminf(v1x, v2x)), xmx = fmaxf(v0x, fmaxf(v1x, v2x));
    float ymn = fminf(v0y, fminf(v1y, v2y)), ymx = fmaxf(v0y, fmaxf(v1y, v2y));
    const float SC = 1.91f, EPS = 1e-3f;
    g_bbox[i] = make_float4(cx + SC * (xmn - cx) - EPS,
                            cx + SC * (xmx - cx) + EPS,
                            cy + SC * (ymn - cy) - EPS,
                            cy + SC * (ymx - cy) + EPS);
}

__global__ void k_face_attr(const int* __restrict__ faces,
                            const float* __restrict__ attribs) {
    int i = blockIdx.x * blockDim.x + threadIdx.x;
    if (i >= NB * NF) return;
    int b = i / NF, f = i % NF;
    float* dst = g_fattr + (size_t)i * 18;
    #pragma unroll
    for (int k = 0; k < 3; k++) {
        int vid = faces[f * 3 + k];
        const float* vn = g_vnorm + ((size_t)b * NV + vid) * 3;
        float x = vn[0], y = vn[1], z = vn[2];
        float d = sqrtf(x * x + y * y + z * z) + 1e-10f;
        dst[k * 6 + 0] = x / d;
        dst[k * 6 + 1] = y / d;
        dst[k * 6 + 2] = z / d;
        const float* at = attribs + ((size_t)i * 3 + k) * 3;
        dst[k * 6 + 3] = at[0];
        dst[k * 6 + 4] = at[1];
        dst[k * 6 + 5] = at[2];
    }
}

__global__ __launch_bounds__(256) void k_raster() {
    const int tile  = blockIdx.x;              // 0..NTILES-1
    const int chunk = blockIdx.y;              // 0..NCHUNK-1
    const int b = tile >> 6;                   // image
    const int t = tile & 63;                   // 8x8 tile grid
    const int tx = (t & 7) << 3, ty = (t >> 3) << 3;

    // warp -> (face-lane, pixel half): fl uniform per warp
    const int w    = threadIdx.x >> 5;
    const int lane = threadIdx.x & 31;
    const int fl   = w & 3;                    // face lane 0..3 (warp-uniform)
    const int half = w >> 2;                   // 0 or 1
    const int pi   = half * 32 + lane;         // pixel 0..63 within tile
    const int lx = pi & 7, ly = pi >> 3;
    const int ix = tx + lx, iy = ty + ly;
    const float px = -1.0f + ix * STEPF;
    const float py = -1.0f + iy * STEPF;
    // warp region: 8 x 4 pixels (rows half*4 .. half*4+3)
    const float wminx = -1.0f + tx * STEPF, wmaxx = wminx + 7.0f * STEPF;
    const float wminy = -1.0f + (ty + half * 4) * STEPF, wmaxy = wminy + 3.0f * STEPF;
    // tile bounds
    const float tminx = wminx, tmaxx = wmaxx;
    const float tminy = -1.0f + ty * STEPF, tmaxy = tminy + 7.0f * STEPF;

    __shared__ int    s_cnt;
    __shared__ float4 s_r0[FCHUNK];
    __shared__ float4 s_r1[FCHUNK];
    __shared__ float4 s_r2[FCHUNK];
    __shared__ float4 s_box[FCHUNK];
    __shared__ short  s_f[FCHUNK];
    __shared__ float  red_S[256];
    __shared__ float  red_z[256];
    __shared__ int    red_i[256];
    if (threadIdx.x == 0) s_cnt = 0;
    __syncthreads();

    const int f0 = chunk * FCHUNK;
    const int f1 = (f0 + FCHUNK < NF) ? (f0 + FCHUNK) : NF;
    const float4* bb   = g_bbox + (size_t)b * NF;
    const float4* recb = g_rec + (size_t)b * NF * 3;
    for (int f = f0 + threadIdx.x; f < f1; f += 256) {
        float4 box = bb[f];
        if (box.x <= tmaxx && box.y >= tminx && box.z <= tmaxy && box.w >= tminy) {
            int k = atomicAdd(&s_cnt, 1);
            s_box[k] = box;
            s_f[k] = (short)f;
            s_r0[k] = recb[f * 3 + 0];
            s_r1[k] = recb[f * 3 + 1];
            s_r2[k] = recb[f * 3 + 2];
        }
    }
    __syncthreads();
    const int cnt = s_cnt;

    const float K1  = 1.0f - 1e-7f;
    const float CIN = log1pf(-K1);           // inside-face contribution

    float S = 0.0f;
    float zb = INFINITY;
    int   ib = 0x7fffffff;

    for (int i = fl; i < cnt; i += 4) {
        float4 box = s_box[i];
        // warp-uniform rejection against this warp's 8x4 region
        if (box.x > wmaxx || box.y < wminx || box.z > wmaxy || box.w < wminy) continue;
        // per-pixel rejection
        if (px < box.x || px > box.y || py < box.z || py > box.w) continue;

        float4 r0 = s_r0[i];
        float4 r1 = s_r1[i];
        float4 r2 = s_r2[i];
        float v0x = r0.x, v0y = r0.y, v1x = r0.z, v1y = r0.w;
        float v2x = r1.x, v2y = r1.y, z0 = r1.z, z1 = r1.w;
        float z2 = r2.x, A = r2.y, invA = r2.z, sgn = r2.w;

        float a0 = (v2x - v1x) * (py - v1y) - (v2y - v1y) * (px - v1x);
        float a1 = (v0x - v2x) * (py - v2y) - (v0y - v2y) * (px - v2x);
        float a2 = (v1x - v0x) * (py - v0y) - (v1y - v0y) * (px - v0x);
        float c0 = a0 * sgn, c1 = a1 * sgn, c2 = a2 * sgn;  // exact sign helpers
        float cmin = fminf(c0, fminf(c1, c2));
        float invAbs = invA * sgn;                           // 1/|A| (exact flip)
        float dmin = cmin * invAbs;                          // = min_i (a_i/A) up to ulps
        if (dmin > -0.3f) {
            if (cmin >= 0.0f) {
                // inside: argmin-critical z path with exact IEEE divisions
                S += CIN;
                float w0 = a0 / A, w1 = a1 / A, w2 = a2 / A;
                float z = w0 * z0 + w1 * z1 + w2 * z2;
                int f = s_f[i];
                if (z > 0.0f && (z < zb || (z == zb && f < ib))) { zb = z; ib = f; }
            } else {
                float tt = fmaxf(dmin * 100.0f, -30.0f);
                float p = __expf(tt) * K1;
                if (p < 0.25f) {
                    S -= p * (1.0f + p * (0.5f + p * (0.33333334f + p * (0.25f + p * 0.2f))));
                } else {
                    S += log1pf(-p);
                }
            }
        }
    }

    // reduce across the 4 face-lanes (deterministic fl order)
    red_S[fl * 64 + pi] = S;
    red_z[fl * 64 + pi] = zb;
    red_i[fl * 64 + pi] = ib;
    __syncthreads();

    if (threadIdx.x < 64) {
        int q = threadIdx.x;              // pixel 0..63
        float Sa = red_S[q];
        float za = red_z[q];
        int   ia = red_i[q];
        #pragma unroll
        for (int l = 1; l < 4; l++) {
            Sa += red_S[l * 64 + q];
            float zo = red_z[l * 64 + q];
            int   io = red_i[l * 64 + q];
            if (zo < za || (zo == za && io < ia)) { za = zo; ia = io; }
        }
        int qx = tx + (q & 7), qy = ty + (q >> 3);
        int p = (b << 12) + (qy << 6) + qx;
        g_ps[chunk * NPIX + p] = Sa;
        g_pz[chunk * NPIX + p] = za;
        g_pi[chunk * NPIX + p] = ia;
    }
}

__global__ void k_combine(float* __restrict__ out) {
    int p = blockIdx.x * blockDim.x + threadIdx.x;
    if (p >= NPIX) return;

    float S = 0.0f;
    float zb = INFINITY;
    int ib = 0x7fffffff;
    #pragma unroll
    for (int c = 0; c < NCHUNK; c++) {
        S += g_ps[c * NPIX + p];
        float z = g_pz[c * NPIX + p];
        int   i = g_pi[c * NPIX + p];
        if (z < zb || (z == zb && i < ib)) { zb = z; ib = i; }
    }
    bool covered = (zb < INFINITY);

    int b = p >> 12, pp = p & 4095, iy = pp >> 6, ix = pp & 63;
    float px = -1.0f + ix * STEPF;
    float py = -1.0f + iy * STEPF;

    float on0 = 0.f, on1 = 0.f, on2 = 0.f;
    float oa0 = 0.f, oa1 = 0.f, oa2 = 0.f;
    float fidx = -1.0f;

    if (covered) {
        const float4* r = g_rec + ((size_t)b * NF + ib) * 3;
        float4 r0 = r[0], r1 = r[1], r2 = r[2];
        float v0x = r0.x, v0y = r0.y, v1x = r0.z, v1y = r0.w;
        float v2x = r1.x, v2y = r1.y;
        float A = r2.y;
        float a0 = (v2x - v1x) * (py - v1y) - (v2y - v1y) * (px - v1x);
        float a1 = (v0x - v2x) * (py - v2y) - (v0y - v2y) * (px - v2x);
        float a2 = (v1x - v0x) * (py - v0y) - (v1y - v0y) * (px - v0x);
        float w0 = a0 / A, w1 = a1 / A, w2 = a2 / A;
        const float* at = g_fattr + ((size_t)b * NF + ib) * 18;
        float att[6];
        #pragma unroll
        for (int c = 0; c < 6; c++)
            att[c] = w0 * at[c] + w1 * at[6 + c] + w2 * at[12 + c];
        float nrm = sqrtf(att[0] * att[0] + att[1] * att[1] + att[2] * att[2]) + 1e-10f;
        on0 = att[0] / nrm; on1 = att[1] / nrm; on2 = att[2] / nrm;
        oa0 = att[3]; oa1 = att[4]; oa2 = att[5];
        fidx = (float)ib;
    }
    float improb = 1.0f - expf(S);

    out[p * 3 + 0] = on0;
    out[p * 3 + 1] = on1;
    out[p * 3 + 2] = on2;
    out[NPIX * 3 + p * 3 + 0] = oa0;
    out[NPIX * 3 + p * 3 + 1] = oa1;
    out[NPIX * 3 + p * 3 + 2] = oa2;
    out[NPIX * 6 + p] = improb;
    out[NPIX * 7 + p] = fidx;
}

// -------- launch --------
extern "C" void kernel_launch(void* const* d_in, const int* in_sizes, int n_in,
                              void* d_out, int out_size) {
    const float* vertices = (const float*)d_in[0];
    const int*   faces    = (const int*)d_in[1];
    const float* attribs  = (const float*)d_in[2];
    const float* cam_rot  = (const float*)d_in[3];
    const float* cam_tr   = (const float*)d_in[4];
    (void)in_sizes; (void)n_in; (void)out_size;

    k_vertices<<<(NB * NV + 255) / 256, 256>>>(vertices, cam_rot, cam_tr);
    k_face_prep<<<(NB * NF + 255) / 256, 256>>>(faces);
    k_face_attr<<<(NB * NF + 255) / 256, 256>>>(faces, attribs);
    k_raster<<<dim3(NTILES, NCHUNK), 256>>>();
    k_combine<<<(NPIX + 255) / 256, 256>>>((float*)d_out);
}

// round 5
// speedup vs baseline: 6.9972x; 1.0894x over previous
#include <cuda_runtime.h>
#include <math.h>
#include <stdint.h>

// Problem constants (fixed by the dataset)
#define NB 4
#define NV 4000
#define NF 6000
#define IMH 64
#define IMW 64
#define NPIX (NB * IMH * IMW)          // 16384
#define NCHUNK 32
#define FCHUNK ((NF + NCHUNK - 1) / NCHUNK)  // 188
#define TILES_PER_IMG 64               // 8x8 grid of 8x8-pixel tiles
#define NTILES (NB * TILES_PER_IMG)    // 256

#define STEPF (2.0f / 63.0f)

// -------- device scratch (no allocations allowed) --------
__device__ float  g_vscam[NB * NV * 3];
__device__ float  g_vsimg[NB * NV * 2];
__device__ float  g_vnorm[NB * NV * 3];
__device__ float4 g_rec[NB * NF * 3];      // packed raster records
__device__ float4 g_bbox[NB * NF];         // dilated bbox (xmin,xmax,ymin,ymax)
__device__ float  g_pz[NCHUNK * NPIX];
__device__ int    g_pi[NCHUNK * NPIX];
__device__ float  g_ps[NCHUNK * NPIX];

// -------- kernels --------
__global__ void k_vertices(const float* __restrict__ verts,
                           const float* __restrict__ rot,
                           const float* __restrict__ trans) {
    int i = blockIdx.x * blockDim.x + threadIdx.x;
    if (i >= NB * NV) return;
    int b = i / NV;
    const float* v = verts + (size_t)i * 3;
    const float* R = rot + b * 9;
    const float* t = trans + b * 3;
    float x = v[0], y = v[1], z = v[2];
    float cx = x * R[0] + y * R[1] + z * R[2] + t[0];
    float cy = x * R[3] + y * R[4] + z * R[5] + t[1];
    float cz = x * R[6] + y * R[7] + z * R[8] + t[2];
    g_vscam[i * 3 + 0] = cx;
    g_vscam[i * 3 + 1] = cy;
    g_vscam[i * 3 + 2] = cz;
    g_vsimg[i * 2 + 0] = cx / cz;
    g_vsimg[i * 2 + 1] = cy / cz;
    g_vnorm[i * 3 + 0] = 0.0f;
    g_vnorm[i * 3 + 1] = 0.0f;
    g_vnorm[i * 3 + 2] = 0.0f;
}

__global__ void k_face_prep(const int* __restrict__ faces) {
    int i = blockIdx.x * blockDim.x + threadIdx.x;
    if (i >= NB * NF) return;
    int b = i / NF, f = i % NF;
    int i0 = faces[f * 3 + 0], i1 = faces[f * 3 + 1], i2 = faces[f * 3 + 2];

    const float* c0 = g_vscam + ((size_t)b * NV + i0) * 3;
    const float* c1 = g_vscam + ((size_t)b * NV + i1) * 3;
    const float* c2 = g_vscam + ((size_t)b * NV + i2) * 3;
    float e1x = c1[0] - c0[0], e1y = c1[1] - c0[1], e1z = c1[2] - c0[2];
    float e2x = c2[0] - c0[0], e2y = c2[1] - c0[1], e2z = c2[2] - c0[2];
    float nx = e1y * e2z - e1z * e2y;
    float ny = e1z * e2x - e1x * e2z;
    float nz = e1x * e2y - e1y * e2x;
    atomicAdd(&g_vnorm[((size_t)b * NV + i0) * 3 + 0], nx);
    atomicAdd(&g_vnorm[((size_t)b * NV + i0) * 3 + 1], ny);
    atomicAdd(&g_vnorm[((size_t)b * NV + i0) * 3 + 2], nz);
    atomicAdd(&g_vnorm[((size_t)b * NV + i1) * 3 + 0], nx);
    atomicAdd(&g_vnorm[((size_t)b * NV + i1) * 3 + 1], ny);
    atomicAdd(&g_vnorm[((size_t)b * NV + i1) * 3 + 2], nz);
    atomicAdd(&g_vnorm[((size_t)b * NV + i2) * 3 + 0], nx);
    atomicAdd(&g_vnorm[((size_t)b * NV + i2) * 3 + 1], ny);
    atomicAdd(&g_vnorm[((size_t)b * NV + i2) * 3 + 2], nz);

    const float* p0 = g_vsimg + ((size_t)b * NV + i0) * 2;
    const float* p1 = g_vsimg + ((size_t)b * NV + i1) * 2;
    const float* p2 = g_vsimg + ((size_t)b * NV + i2) * 2;
    float v0x = p0[0], v0y = p0[1];
    float v1x = p1[0], v1y = p1[1];
    float v2x = p2[0], v2y = p2[1];
    float A = (v1x - v0x) * (v2y - v0y) - (v1y - v0y) * (v2x - v0x);
    if (fabsf(A) < 1e-8f) A = 1e-8f;
    float invA = 1.0f / A;
    float sgn  = (A > 0.0f) ? 1.0f : -1.0f;

    float4* r = g_rec + (size_t)i * 3;
    r[0] = make_float4(v0x, v0y, v1x, v1y);
    r[1] = make_float4(v2x, v2y, c0[2], c1[2]);
    r[2] = make_float4(c2[2], A, invA, sgn);

    // dilated bbox: {min_i w_i >= -0.3} == triangle scaled x1.9 about centroid
    float cx = (v0x + v1x + v2x) * 0.33333334f;
    float cy = (v0y + v1y + v2y) * 0.33333334f;
    float xmn = fminf(v0x, fminf(v1x, v2x)), xmx = fmaxf(v0x, fmaxf(v1x, v2x));
    float ymn = fminf(v0y, fminf(v1y, v2y)), ymx = fmaxf(v0y, fmaxf(v1y, v2y));
    const float SC = 1.91f, EPS = 1e-3f;
    g_bbox[i] = make_float4(cx + SC * (xmn - cx) - EPS,
                            cx + SC * (xmx - cx) + EPS,
                            cy + SC * (ymn - cy) - EPS,
                            cy + SC * (ymx - cy) + EPS);
}

__global__ __launch_bounds__(256) void k_raster() {
    const int tile  = blockIdx.x;              // 0..NTILES-1
    const int chunk = blockIdx.y;              // 0..NCHUNK-1
    const int b = tile >> 6;                   // image
    const int t = tile & 63;                   // 8x8 tile grid
    const int tx = (t & 7) << 3, ty = (t >> 3) << 3;

    // warp -> (face-lane, pixel half): fl uniform per warp
    const int w    = threadIdx.x >> 5;
    const int lane = threadIdx.x & 31;
    const int fl   = w & 3;                    // face lane 0..3 (warp-uniform)
    const int half = w >> 2;                   // 0 or 1
    const int pi   = half * 32 + lane;         // pixel 0..63 within tile
    const int lx = pi & 7, ly = pi >> 3;
    const int ix = tx + lx, iy = ty + ly;
    const float px = -1.0f + ix * STEPF;
    const float py = -1.0f + iy * STEPF;
    // warp region: 8 x 4 pixels (rows half*4 .. half*4+3)
    const float wminx = -1.0f + tx * STEPF, wmaxx = wminx + 7.0f * STEPF;
    const float wminy = -1.0f + (ty + half * 4) * STEPF, wmaxy = wminy + 3.0f * STEPF;
    // tile bounds
    const float tminx = wminx, tmaxx = wmaxx;
    const float tminy = -1.0f + ty * STEPF, tmaxy = tminy + 7.0f * STEPF;

    __shared__ int    s_cnt;
    __shared__ float4 s_r0[FCHUNK];
    __shared__ float4 s_r1[FCHUNK];
    __shared__ float4 s_r2[FCHUNK];
    __shared__ float4 s_box[FCHUNK];
    __shared__ short  s_f[FCHUNK];
    __shared__ float  red_S[256];
    __shared__ float  red_z[256];
    __shared__ int    red_i[256];
    if (threadIdx.x == 0) s_cnt = 0;
    __syncthreads();

    const int f0 = chunk * FCHUNK;
    const int f1 = (f0 + FCHUNK < NF) ? (f0 + FCHUNK) : NF;
    const float4* bb   = g_bbox + (size_t)b * NF;
    const float4* recb = g_rec + (size_t)b * NF * 3;
    for (int f = f0 + threadIdx.x; f < f1; f += 256) {
        float4 box = bb[f];
        if (box.x <= tmaxx && box.y >= tminx && box.z <= tmaxy && box.w >= tminy) {
            int k = atomicAdd(&s_cnt, 1);
            s_box[k] = box;
            s_f[k] = (short)f;
            s_r0[k] = recb[f * 3 + 0];
            s_r1[k] = recb[f * 3 + 1];
            s_r2[k] = recb[f * 3 + 2];
        }
    }
    __syncthreads();
    const int cnt = s_cnt;

    const float K1  = 1.0f - 1e-7f;
    const float CIN = log1pf(-K1);           // inside-face contribution

    float S = 0.0f;
    float zb = INFINITY;
    int   ib = 0x7fffffff;

    for (int i = fl; i < cnt; i += 4) {
        float4 box = s_box[i];
        // warp-uniform rejection against this warp's 8x4 region
        if (box.x > wmaxx || box.y < wminx || box.z > wmaxy || box.w < wminy) continue;
        // per-pixel rejection
        if (px < box.x || px > box.y || py < box.z || py > box.w) continue;

        float4 r0 = s_r0[i];
        float4 r1 = s_r1[i];
        float4 r2 = s_r2[i];
        float v0x = r0.x, v0y = r0.y, v1x = r0.z, v1y = r0.w;
        float v2x = r1.x, v2y = r1.y, z0 = r1.z, z1 = r1.w;
        float z2 = r2.x, A = r2.y, invA = r2.z, sgn = r2.w;

        float a0 = (v2x - v1x) * (py - v1y) - (v2y - v1y) * (px - v1x);
        float a1 = (v0x - v2x) * (py - v2y) - (v0y - v2y) * (px - v2x);
        float a2 = (v1x - v0x) * (py - v0y) - (v1y - v0y) * (px - v0x);
        float c0 = a0 * sgn, c1 = a1 * sgn, c2 = a2 * sgn;  // exact sign helpers
        float cmin = fminf(c0, fminf(c1, c2));
        float invAbs = invA * sgn;                           // 1/|A| (exact flip)
        float dmin = cmin * invAbs;                          // = min_i (a_i/A) up to ulps
        if (dmin > -0.3f) {
            if (cmin >= 0.0f) {
                // inside: argmin-critical z path with exact IEEE divisions
                S += CIN;
                float w0 = a0 / A, w1 = a1 / A, w2 = a2 / A;
                float z = w0 * z0 + w1 * z1 + w2 * z2;
                int f = s_f[i];
                if (z > 0.0f && (z < zb || (z == zb && f < ib))) { zb = z; ib = f; }
            } else {
                // branch-free soft-coverage: ln(1 - p), abs err <= ~1e-5 where
                // output is sensitive (error grows only where improb saturates)
                float tt = fmaxf(dmin * 100.0f, -30.0f);
                float p = __expf(tt) * K1;
                S += __logf(1.0f - p);
            }
        }
    }

    // reduce across the 4 face-lanes (deterministic fl order)
    red_S[fl * 64 + pi] = S;
    red_z[fl * 64 + pi] = zb;
    red_i[fl * 64 + pi] = ib;
    __syncthreads();

    if (threadIdx.x < 64) {
        int q = threadIdx.x;              // pixel 0..63
        float Sa = red_S[q];
        float za = red_z[q];
        int   ia = red_i[q];
        #pragma unroll
        for (int l = 1; l < 4; l++) {
            Sa += red_S[l * 64 + q];
            float zo = red_z[l * 64 + q];
            int   io = red_i[l * 64 + q];
            if (zo < za || (zo == za && io < ia)) { za = zo; ia = io; }
        }
        int qx = tx + (q & 7), qy = ty + (q >> 3);
        int p = (b << 12) + (qy << 6) + qx;
        g_ps[chunk * NPIX + p] = Sa;
        g_pz[chunk * NPIX + p] = za;
        g_pi[chunk * NPIX + p] = ia;
    }
}

__global__ void k_combine(const int* __restrict__ faces,
                          const float* __restrict__ attribs,
                          float* __restrict__ out) {
    int p = blockIdx.x * blockDim.x + threadIdx.x;
    if (p >= NPIX) return;

    float S = 0.0f;
    float zb = INFINITY;
    int ib = 0x7fffffff;
    #pragma unroll
    for (int c = 0; c < NCHUNK; c++) {
        S += g_ps[c * NPIX + p];
        float z = g_pz[c * NPIX + p];
        int   i = g_pi[c * NPIX + p];
        if (z < zb || (z == zb && i < ib)) { zb = z; ib = i; }
    }
    bool covered = (zb < INFINITY);

    int b = p >> 12, pp = p & 4095, iy = pp >> 6, ix = pp & 63;
    float px = -1.0f + ix * STEPF;
    float py = -1.0f + iy * STEPF;

    float on0 = 0.f, on1 = 0.f, on2 = 0.f;
    float oa0 = 0.f, oa1 = 0.f, oa2 = 0.f;
    float fidx = -1.0f;

    if (covered) {
        const float4* r = g_rec + ((size_t)b * NF + ib) * 3;
        float4 r0 = r[0], r1 = r[1], r2 = r[2];
        float v0x = r0.x, v0y = r0.y, v1x = r0.z, v1y = r0.w;
        float v2x = r1.x, v2y = r1.y;
        float A = r2.y;
        float a0 = (v2x - v1x) * (py - v1y) - (v2y - v1y) * (px - v1x);
        float a1 = (v0x - v2x) * (py - v2y) - (v0y - v2y) * (px - v2x);
        float a2 = (v1x - v0x) * (py - v0y) - (v1y - v0y) * (px - v0x);
        float w0 = a0 / A, w1 = a1 / A, w2 = a2 / A;

        // gather winning face's per-vertex attributes directly
        float att[6] = {0.f, 0.f, 0.f, 0.f, 0.f, 0.f};
        float wk[3] = {w0, w1, w2};
        #pragma unroll
        for (int k = 0; k < 3; k++) {
            int vid = faces[ib * 3 + k];
            const float* vn = g_vnorm + ((size_t)b * NV + vid) * 3;
            float x = vn[0], y = vn[1], z = vn[2];
            float d = sqrtf(x * x + y * y + z * z) + 1e-10f;
            att[0] += wk[k] * (x / d);
            att[1] += wk[k] * (y / d);
            att[2] += wk[k] * (z / d);
            const float* at = attribs + (((size_t)b * NF + ib) * 3 + k) * 3;
            att[3] += wk[k] * at[0];
            att[4] += wk[k] * at[1];
            att[5] += wk[k] * at[2];
        }
        float nrm = sqrtf(att[0] * att[0] + att[1] * att[1] + att[2] * att[2]) + 1e-10f;
        on0 = att[0] / nrm; on1 = att[1] / nrm; on2 = att[2] / nrm;
        oa0 = att[3]; oa1 = att[4]; oa2 = att[5];
        fidx = (float)ib;
    }
    float improb = 1.0f - expf(S);

    out[p * 3 + 0] = on0;
    out[p * 3 + 1] = on1;
    out[p * 3 + 2] = on2;
    out[NPIX * 3 + p * 3 + 0] = oa0;
    out[NPIX * 3 + p * 3 + 1] = oa1;
    out[NPIX * 3 + p * 3 + 2] = oa2;
    out[NPIX * 6 + p] = improb;
    out[NPIX * 7 + p] = fidx;
}

// -------- launch --------
extern "C" void kernel_launch(void* const* d_in, const int* in_sizes, int n_in,
                              void* d_out, int out_size) {
    const float* vertices = (const float*)d_in[0];
    const int*   faces    = (const int*)d_in[1];
    const float* attribs  = (const float*)d_in[2];
    const float* cam_rot  = (const float*)d_in[3];
    const float* cam_tr   = (const float*)d_in[4];
    (void)in_sizes; (void)n_in; (void)out_size;

    k_vertices<<<(NB * NV + 255) / 256, 256>>>(vertices, cam_rot, cam_tr);
    k_face_prep<<<(NB * NF + 255) / 256, 256>>>(faces);
    k_raster<<<dim3(NTILES, NCHUNK), 256>>>();
    k_combine<<<(NPIX + 255) / 256, 256>>>(faces, attribs, (float*)d_out);
}

// round 6
// speedup vs baseline: 7.7196x; 1.1032x over previous
#include <cuda_runtime.h>
#include <math.h>
#include <stdint.h>

// Problem constants (fixed by the dataset)
#define NB 4
#define NV 4000
#define NF 6000
#define IMH 64
#define IMW 64
#define NPIX (NB * IMH * IMW)          // 16384
#define NCHUNK 32
#define FCHUNK ((NF + NCHUNK - 1) / NCHUNK)  // 188
#define TILES_PER_IMG 64               // 8x8 grid of 8x8-pixel tiles
#define NTILES (NB * TILES_PER_IMG)    // 256

#define STEPF (2.0f / 63.0f)
#define ZKEY_INIT 0xFFFFFFFFFFFFFFFFull

// -------- device scratch (no allocations allowed) --------
__device__ float              g_vscam[NB * NV * 3];
__device__ float              g_vsimg[NB * NV * 2];
__device__ float              g_vnorm[NB * NV * 3];
__device__ float4             g_rec[NB * NF * 3];   // packed raster records
__device__ float4             g_bbox[NB * NF];      // dilated bbox
__device__ float              g_accS[NPIX];         // soft-coverage log-sum
__device__ unsigned long long g_accZ[NPIX];         // packed (z_bits<<32)|face

// -------- kernels --------
__global__ void k_vertices(const float* __restrict__ verts,
                           const float* __restrict__ rot,
                           const float* __restrict__ trans) {
    int i = blockIdx.x * blockDim.x + threadIdx.x;
    if (i >= NB * NV) return;
    int b = i / NV;
    const float* v = verts + (size_t)i * 3;
    const float* R = rot + b * 9;
    const float* t = trans + b * 3;
    float x = v[0], y = v[1], z = v[2];
    float cx = x * R[0] + y * R[1] + z * R[2] + t[0];
    float cy = x * R[3] + y * R[4] + z * R[5] + t[1];
    float cz = x * R[6] + y * R[7] + z * R[8] + t[2];
    g_vscam[i * 3 + 0] = cx;
    g_vscam[i * 3 + 1] = cy;
    g_vscam[i * 3 + 2] = cz;
    g_vsimg[i * 2 + 0] = cx / cz;
    g_vsimg[i * 2 + 1] = cy / cz;
    g_vnorm[i * 3 + 0] = 0.0f;
    g_vnorm[i * 3 + 1] = 0.0f;
    g_vnorm[i * 3 + 2] = 0.0f;
}

__global__ void k_face_prep(const int* __restrict__ faces) {
    int i = blockIdx.x * blockDim.x + threadIdx.x;
    if (i >= NB * NF) return;
    // init per-pixel accumulators (NPIX=16384 < NB*NF=24000 threads)
    if (i < NPIX) {
        g_accS[i] = 0.0f;
        g_accZ[i] = ZKEY_INIT;
    }
    int b = i / NF, f = i % NF;
    int i0 = faces[f * 3 + 0], i1 = faces[f * 3 + 1], i2 = faces[f * 3 + 2];

    const float* c0 = g_vscam + ((size_t)b * NV + i0) * 3;
    const float* c1 = g_vscam + ((size_t)b * NV + i1) * 3;
    const float* c2 = g_vscam + ((size_t)b * NV + i2) * 3;
    float e1x = c1[0] - c0[0], e1y = c1[1] - c0[1], e1z = c1[2] - c0[2];
    float e2x = c2[0] - c0[0], e2y = c2[1] - c0[1], e2z = c2[2] - c0[2];
    float nx = e1y * e2z - e1z * e2y;
    float ny = e1z * e2x - e1x * e2z;
    float nz = e1x * e2y - e1y * e2x;
    atomicAdd(&g_vnorm[((size_t)b * NV + i0) * 3 + 0], nx);
    atomicAdd(&g_vnorm[((size_t)b * NV + i0) * 3 + 1], ny);
    atomicAdd(&g_vnorm[((size_t)b * NV + i0) * 3 + 2], nz);
    atomicAdd(&g_vnorm[((size_t)b * NV + i1) * 3 + 0], nx);
    atomicAdd(&g_vnorm[((size_t)b * NV + i1) * 3 + 1], ny);
    atomicAdd(&g_vnorm[((size_t)b * NV + i1) * 3 + 2], nz);
    atomicAdd(&g_vnorm[((size_t)b * NV + i2) * 3 + 0], nx);
    atomicAdd(&g_vnorm[((size_t)b * NV + i2) * 3 + 1], ny);
    atomicAdd(&g_vnorm[((size_t)b * NV + i2) * 3 + 2], nz);

    const float* p0 = g_vsimg + ((size_t)b * NV + i0) * 2;
    const float* p1 = g_vsimg + ((size_t)b * NV + i1) * 2;
    const float* p2 = g_vsimg + ((size_t)b * NV + i2) * 2;
    float v0x = p0[0], v0y = p0[1];
    float v1x = p1[0], v1y = p1[1];
    float v2x = p2[0], v2y = p2[1];
    float A = (v1x - v0x) * (v2y - v0y) - (v1y - v0y) * (v2x - v0x);
    if (fabsf(A) < 1e-8f) A = 1e-8f;
    float invA = 1.0f / A;
    float sgn  = (A > 0.0f) ? 1.0f : -1.0f;

    float4* r = g_rec + (size_t)i * 3;
    r[0] = make_float4(v0x, v0y, v1x, v1y);
    r[1] = make_float4(v2x, v2y, c0[2], c1[2]);
    r[2] = make_float4(c2[2], A, invA, sgn);

    // dilated bbox: {min_i w_i >= -0.3} == triangle scaled x1.9 about centroid
    float cx = (v0x + v1x + v2x) * 0.33333334f;
    float cy = (v0y + v1y + v2y) * 0.33333334f;
    float xmn = fminf(v0x, fminf(v1x, v2x)), xmx = fmaxf(v0x, fmaxf(v1x, v2x));
    float ymn = fminf(v0y, fminf(v1y, v2y)), ymx = fmaxf(v0y, fmaxf(v1y, v2y));
    const float SC = 1.91f, EPS = 1e-3f;
    g_bbox[i] = make_float4(cx + SC * (xmn - cx) - EPS,
                            cx + SC * (xmx - cx) + EPS,
                            cy + SC * (ymn - cy) - EPS,
                            cy + SC * (ymx - cy) + EPS);
}

__global__ __launch_bounds__(256) void k_raster() {
    const int tile  = blockIdx.x;              // 0..NTILES-1
    const int chunk = blockIdx.y;              // 0..NCHUNK-1
    const int b = tile >> 6;                   // image
    const int t = tile & 63;                   // 8x8 tile grid
    const int tx = (t & 7) << 3, ty = (t >> 3) << 3;

    // warp -> (face-lane, pixel half): fl uniform per warp
    const int w    = threadIdx.x >> 5;
    const int lane = threadIdx.x & 31;
    const int fl   = w & 3;                    // face lane 0..3 (warp-uniform)
    const int half = w >> 2;                   // 0 or 1
    const int pi   = half * 32 + lane;         // pixel 0..63 within tile
    const int lx = pi & 7, ly = pi >> 3;
    const int ix = tx + lx, iy = ty + ly;
    const float px = -1.0f + ix * STEPF;
    const float py = -1.0f + iy * STEPF;
    // warp region: 8 x 4 pixels (rows half*4 .. half*4+3)
    const float wminx = -1.0f + tx * STEPF, wmaxx = wminx + 7.0f * STEPF;
    const float wminy = -1.0f + (ty + half * 4) * STEPF, wmaxy = wminy + 3.0f * STEPF;
    // tile bounds
    const float tminx = wminx, tmaxx = wmaxx;
    const float tminy = -1.0f + ty * STEPF, tmaxy = tminy + 7.0f * STEPF;

    __shared__ int    s_cnt;
    __shared__ float4 s_r0[FCHUNK];
    __shared__ float4 s_r1[FCHUNK];
    __shared__ float4 s_r2[FCHUNK];
    __shared__ float4 s_box[FCHUNK];
    __shared__ short  s_f[FCHUNK];
    __shared__ float  red_S[256];
    __shared__ float  red_z[256];
    __shared__ int    red_i[256];
    if (threadIdx.x == 0) s_cnt = 0;
    __syncthreads();

    const int f0 = chunk * FCHUNK;
    const int f1 = (f0 + FCHUNK < NF) ? (f0 + FCHUNK) : NF;
    const float4* bb   = g_bbox + (size_t)b * NF;
    const float4* recb = g_rec + (size_t)b * NF * 3;
    for (int f = f0 + threadIdx.x; f < f1; f += 256) {
        float4 box = bb[f];
        if (box.x <= tmaxx && box.y >= tminx && box.z <= tmaxy && box.w >= tminy) {
            int k = atomicAdd(&s_cnt, 1);
            s_box[k] = box;
            s_f[k] = (short)f;
            s_r0[k] = recb[f * 3 + 0];
            s_r1[k] = recb[f * 3 + 1];
            s_r2[k] = recb[f * 3 + 2];
        }
    }
    __syncthreads();
    const int cnt = s_cnt;

    const float K1  = 1.0f - 1e-7f;
    const float CIN = log1pf(-K1);           // inside-face contribution

    float S = 0.0f;
    float zb = INFINITY;
    int   ib = 0x7fffffff;

    for (int i = fl; i < cnt; i += 4) {
        float4 box = s_box[i];
        // warp-uniform rejection against this warp's 8x4 region
        if (box.x > wmaxx || box.y < wminx || box.z > wmaxy || box.w < wminy) continue;
        // per-pixel rejection
        if (px < box.x || px > box.y || py < box.z || py > box.w) continue;

        float4 r0 = s_r0[i];
        float4 r1 = s_r1[i];
        float4 r2 = s_r2[i];
        float v0x = r0.x, v0y = r0.y, v1x = r0.z, v1y = r0.w;
        float v2x = r1.x, v2y = r1.y, z0 = r1.z, z1 = r1.w;
        float z2 = r2.x, A = r2.y, invA = r2.z, sgn = r2.w;

        float a0 = (v2x - v1x) * (py - v1y) - (v2y - v1y) * (px - v1x);
        float a1 = (v0x - v2x) * (py - v2y) - (v0y - v2y) * (px - v2x);
        float a2 = (v1x - v0x) * (py - v0y) - (v1y - v0y) * (px - v0x);
        float c0 = a0 * sgn, c1 = a1 * sgn, c2 = a2 * sgn;  // exact sign helpers
        float cmin = fminf(c0, fminf(c1, c2));
        float invAbs = invA * sgn;                           // 1/|A| (exact flip)
        float dmin = cmin * invAbs;                          // = min_i (a_i/A) up to ulps
        if (dmin > -0.3f) {
            if (cmin >= 0.0f) {
                // inside: argmin-critical z path with exact IEEE divisions
                S += CIN;
                float w0 = a0 / A, w1 = a1 / A, w2 = a2 / A;
                float z = w0 * z0 + w1 * z1 + w2 * z2;
                int f = s_f[i];
                if (z > 0.0f && (z < zb || (z == zb && f < ib))) { zb = z; ib = f; }
            } else {
                // branch-free soft-coverage: ln(1 - p)
                float tt = fmaxf(dmin * 100.0f, -30.0f);
                float p = __expf(tt) * K1;
                S += __logf(1.0f - p);
            }
        }
    }

    // reduce across the 4 face-lanes (deterministic fl order)
    red_S[fl * 64 + pi] = S;
    red_z[fl * 64 + pi] = zb;
    red_i[fl * 64 + pi] = ib;
    __syncthreads();

    if (threadIdx.x < 64) {
        int q = threadIdx.x;              // pixel 0..63
        float Sa = red_S[q];
        float za = red_z[q];
        int   ia = red_i[q];
        #pragma unroll
        for (int l = 1; l < 4; l++) {
            Sa += red_S[l * 64 + q];
            float zo = red_z[l * 64 + q];
            int   io = red_i[l * 64 + q];
            if (zo < za || (zo == za && io < ia)) { za = zo; ia = io; }
        }
        int qx = tx + (q & 7), qy = ty + (q >> 3);
        int p = (b << 12) + (qy << 6) + qx;
        // packed lex-min: (z_bits<<32)|face — exact (z, idx) argmin semantics
        if (ia != 0x7fffffff) {
            unsigned long long key =
                ((unsigned long long)__float_as_uint(za) << 32) | (unsigned int)ia;
            atomicMin(&g_accZ[p], key);
        }
        if (Sa != 0.0f) atomicAdd(&g_accS[p], Sa);
    }
}

__global__ void k_combine(const int* __restrict__ faces,
                          const float* __restrict__ attribs,
                          float* __restrict__ out) {
    int p = blockIdx.x * blockDim.x + threadIdx.x;
    if (p >= NPIX) return;

    float S = g_accS[p];
    unsigned long long key = g_accZ[p];
    bool covered = (key != ZKEY_INIT);

    int b = p >> 12, pp = p & 4095, iy = pp >> 6, ix = pp & 63;
    float px = -1.0f + ix * STEPF;
    float py = -1.0f + iy * STEPF;

    float on0 = 0.f, on1 = 0.f, on2 = 0.f;
    float oa0 = 0.f, oa1 = 0.f, oa2 = 0.f;
    float fidx = -1.0f;

    if (covered) {
        int ib = (int)(key & 0xFFFFFFFFu);
        const float4* r = g_rec + ((size_t)b * NF + ib) * 3;
        float4 r0 = r[0], r1 = r[1];
        float v0x = r0.x, v0y = r0.y, v1x = r0.z, v1y = r0.w;
        float v2x = r1.x, v2y = r1.y;
        float A = r[2].y;
        float a0 = (v2x - v1x) * (py - v1y) - (v2y - v1y) * (px - v1x);
        float a1 = (v0x - v2x) * (py - v2y) - (v0y - v2y) * (px - v2x);
        float a2 = (v1x - v0x) * (py - v0y) - (v1y - v0y) * (px - v0x);
        float w0 = a0 / A, w1 = a1 / A, w2 = a2 / A;

        // gather winning face's per-vertex attributes directly
        float att[6] = {0.f, 0.f, 0.f, 0.f, 0.f, 0.f};
        float wk[3] = {w0, w1, w2};
        #pragma unroll
        for (int k = 0; k < 3; k++) {
            int vid = faces[ib * 3 + k];
            const float* vn = g_vnorm + ((size_t)b * NV + vid) * 3;
            float x = vn[0], y = vn[1], z = vn[2];
            float d = sqrtf(x * x + y * y + z * z) + 1e-10f;
            att[0] += wk[k] * (x / d);
            att[1] += wk[k] * (y / d);
            att[2] += wk[k] * (z / d);
            const float* at = attribs + (((size_t)b * NF + ib) * 3 + k) * 3;
            att[3] += wk[k] * at[0];
            att[4] += wk[k] * at[1];
            att[5] += wk[k] * at[2];
        }
        float nrm = sqrtf(att[0] * att[0] + att[1] * att[1] + att[2] * att[2]) + 1e-10f;
        on0 = att[0] / nrm; on1 = att[1] / nrm; on2 = att[2] / nrm;
        oa0 = att[3]; oa1 = att[4]; oa2 = att[5];
        fidx = (float)ib;
    }
    float improb = 1.0f - expf(S);

    out[p * 3 + 0] = on0;
    out[p * 3 + 1] = on1;
    out[p * 3 + 2] = on2;
    out[NPIX * 3 + p * 3 + 0] = oa0;
    out[NPIX * 3 + p * 3 + 1] = oa1;
    out[NPIX * 3 + p * 3 + 2] = oa2;
    out[NPIX * 6 + p] = improb;
    out[NPIX * 7 + p] = fidx;
}

// -------- launch --------
extern "C" void kernel_launch(void* const* d_in, const int* in_sizes, int n_in,
                              void* d_out, int out_size) {
    const float* vertices = (const float*)d_in[0];
    const int*   faces    = (const int*)d_in[1];
    const float* attribs  = (const float*)d_in[2];
    const float* cam_rot  = (const float*)d_in[3];
    const float* cam_tr   = (const float*)d_in[4];
    (void)in_sizes; (void)n_in; (void)out_size;

    k_vertices<<<(NB * NV + 255) / 256, 256>>>(vertices, cam_rot, cam_tr);
    k_face_prep<<<(NB * NF + 255) / 256, 256>>>(faces);
    k_raster<<<dim3(NTILES, NCHUNK), 256>>>();
    k_combine<<<(NPIX + 255) / 256, 256>>>(faces, attribs, (float*)d_out);
}